// round 12
// baseline (speedup 1.0000x reference)
#include <cuda_runtime.h>
#include <cuda_fp16.h>
#include <cstdint>

#define K_DIM 4096
#define N_DIM 4096
#define NG    512
#define M_MAX 8192

// ---- GEMM tiling (fp16 operands) ----
#define BM 128
#define BN 128
#define BKH 64                  // halves per k-stage = 128 B per row (SW128 domain)
#define NSTAGES 3
#define NTHREADS 128            // 4 warps, each 64x64
#define STAGE_A 16384           // 128 rows x 128 B
#define STAGE_B 16384
#define STAGE_BYTES (STAGE_A + STAGE_B)

#define HCLAMP 65472.0f

// Scratch (static __device__: allowed)
__device__ __half g_X[(size_t)M_MAX * K_DIM];   // x * alpha_k, fp16      [M,K]
__device__ __half g_B[(size_t)N_DIM * K_DIM];   // W / alpha_k, fp16, K-major [N,K]
__device__ float  g_alpha[K_DIM];               // per-k power-of-2 rebalance
__device__ int    g_lab64;

// ---------------- helpers ----------------
__device__ __forceinline__ uint32_t smem_u32(const void* p) {
    uint32_t a;
    asm("{ .reg .u64 t; cvta.to.shared.u64 t, %1; cvt.u32.u64 %0, t; }" : "=r"(a) : "l"(p));
    return a;
}
__device__ __forceinline__ void cp16(uint32_t saddr, const void* g) {
    asm volatile("cp.async.cg.shared.global [%0], [%1], 16;" :: "r"(saddr), "l"(g));
}
__device__ __forceinline__ void ldsm4(uint32_t& r0, uint32_t& r1, uint32_t& r2, uint32_t& r3,
                                      uint32_t addr) {
    asm volatile("ldmatrix.sync.aligned.m8n8.x4.shared.b16 {%0,%1,%2,%3}, [%4];"
                 : "=r"(r0), "=r"(r1), "=r"(r2), "=r"(r3) : "r"(addr));
}
__device__ __forceinline__ float hclamp(float v) {
    return fminf(fmaxf(v, -HCLAMP), HCLAMP);
}
__device__ __forceinline__ uint32_t h2_bits(__half2 h) {
    uint32_t u;
    memcpy(&u, &h, 4);
    return u;
}

// ---------------------------------------------------------------------------
// setup: per-k alpha (all threads) + warp-ballot label dtype detection.
// alpha_k = 2^e, e = clamp(ceil(-log2(max(scale,1e-8))/2), 0, 12)
// Detection: int64 LE labels < 65536 => every odd int32 word == 0. The 64
// probe words are loaded by one warp in parallel (one L2 trip, not 64).
// ---------------------------------------------------------------------------
__global__ void setup_kernel(const int* __restrict__ labels32,
                             const float* __restrict__ scale) {
    int k = blockIdx.x * blockDim.x + threadIdx.x;
    if (k < K_DIM) {
        float s = fmaxf(scale[k], 1e-8f);
        int e = (int)ceilf(-0.5f * log2f(s));
        e = max(0, min(12, e));
        g_alpha[k] = (float)(1u << e);
    }
    if (blockIdx.x == 0 && threadIdx.x < 32) {
        int t = threadIdx.x;
        int w0 = labels32[2 * t + 1];
        int w1 = labels32[2 * (t + 32) + 1];
        unsigned m = __ballot_sync(0xFFFFFFFFu, (w0 | w1) != 0);
        if (t == 0) g_lab64 = (m == 0) ? 1 : 0;
    }
}

// ---------------------------------------------------------------------------
// dequant + transpose: g_B[n][k] = fp16( centroids[labels[k,n/8]][n%8] /
//                                        (max(scale[k],1e-8) * alpha_k) )
// ---------------------------------------------------------------------------
__global__ void __launch_bounds__(256) dequant_kernel(const float* __restrict__ centroids,
                                                      const void* __restrict__ labels_raw,
                                                      const float* __restrict__ scale) {
    __shared__ float tile[128][65];
    const int tid = threadIdx.x;
    const int k0 = blockIdx.x * 64;
    const int n0 = blockIdx.y * 128;
    const int g0 = n0 >> 3;
    const bool l64 = (g_lab64 != 0);

    #pragma unroll
    for (int it = 0; it < 4; it++) {
        int id = it * 256 + tid;          // 1024 items: 64 k x 16 groups
        int kl = id >> 4, g = id & 15;
        int k = k0 + kl;
        long long lab = l64 ? ((const long long*)labels_raw)[(size_t)k * NG + g0 + g]
                            : (long long)((const int*)labels_raw)[(size_t)k * NG + g0 + g];
        float rs = 1.0f / (fmaxf(__ldg(scale + k), 1e-8f) * g_alpha[k]);
        const float4* c = reinterpret_cast<const float4*>(centroids + (size_t)lab * 8);
        float4 v0 = __ldg(c), v1 = __ldg(c + 1);
        int nb = g * 8;
        tile[nb + 0][kl] = v0.x * rs; tile[nb + 1][kl] = v0.y * rs;
        tile[nb + 2][kl] = v0.z * rs; tile[nb + 3][kl] = v0.w * rs;
        tile[nb + 4][kl] = v1.x * rs; tile[nb + 5][kl] = v1.y * rs;
        tile[nb + 6][kl] = v1.z * rs; tile[nb + 7][kl] = v1.w * rs;
    }
    __syncthreads();
    #pragma unroll
    for (int it = 0; it < 8; it++) {
        int id = it * 256 + tid;          // 2048 items: 128 n x 16 k-quads
        int nl = id >> 4, k4 = (id & 15) * 4;
        __half2 h0 = __floats2half2_rn(hclamp(tile[nl][k4]),     hclamp(tile[nl][k4 + 1]));
        __half2 h1 = __floats2half2_rn(hclamp(tile[nl][k4 + 2]), hclamp(tile[nl][k4 + 3]));
        uint2 v = make_uint2(h2_bits(h0), h2_bits(h1));
        *reinterpret_cast<uint2*>(g_B + (size_t)(n0 + nl) * K_DIM + k0 + k4) = v;
    }
}

// ---------------------------------------------------------------------------
// x' = fp16(x * alpha_k): 8 halves per thread
// ---------------------------------------------------------------------------
__global__ void round_x_kernel(const float* __restrict__ x, int n8) {
    int idx = blockIdx.x * blockDim.x + threadIdx.x;
    if (idx >= n8) return;
    const int kb = (idx * 8) & (K_DIM - 1);
    float4 a = __ldg(reinterpret_cast<const float4*>(x) + idx * 2);
    float4 b = __ldg(reinterpret_cast<const float4*>(x) + idx * 2 + 1);
    float4 al0 = *reinterpret_cast<const float4*>(g_alpha + kb);
    float4 al1 = *reinterpret_cast<const float4*>(g_alpha + kb + 4);
    __half2 h0 = __floats2half2_rn(hclamp(a.x * al0.x), hclamp(a.y * al0.y));
    __half2 h1 = __floats2half2_rn(hclamp(a.z * al0.z), hclamp(a.w * al0.w));
    __half2 h2 = __floats2half2_rn(hclamp(b.x * al1.x), hclamp(b.y * al1.y));
    __half2 h3 = __floats2half2_rn(hclamp(b.z * al1.z), hclamp(b.w * al1.w));
    uint4 v = make_uint4(h2_bits(h0), h2_bits(h1), h2_bits(h2), h2_bits(h3));
    reinterpret_cast<uint4*>(g_X)[idx] = v;
}

// ---------------------------------------------------------------------------
// GEMM: out = g_X @ g_B^T + bias.  128x128 CTA tile, 4 warps of 64x64,
// BK=64 halves, 3-stage cp.async, SW128 swizzled smem, ldmatrix with
// register-level double buffering, m16n8k16 fp16 mma.sync, fp32 accumulate.
// cp.async issue for stage t+2 is deferred past the kk=0 MMA block so the
// tensor pipe restarts immediately at each tile head.
// ---------------------------------------------------------------------------
__global__ void __launch_bounds__(NTHREADS, 2)
gemm_kernel(const float* __restrict__ bias, float* __restrict__ out) {
    extern __shared__ char smem_raw[];
    const uint32_t sb = smem_u32(smem_raw);

    const int tid  = threadIdx.x;
    const int wid  = tid >> 5;
    const int lane = tid & 31;
    const int bm = blockIdx.y * BM;
    const int bn = blockIdx.x * BN;
    const int wm = (wid & 1) * 64;        // warp tile 64 (m) x 64 (n)
    const int wn = (wid >> 1) * 64;

    float c[4][8][4];
    #pragma unroll
    for (int mi = 0; mi < 4; mi++)
        #pragma unroll
        for (int ni = 0; ni < 8; ni++) {
            c[mi][ni][0] = 0.f; c[mi][ni][1] = 0.f;
            c[mi][ni][2] = 0.f; c[mi][ni][3] = 0.f;
        }

    const int KT = K_DIM / BKH;           // 64

    const __half* gA0 = g_X + (size_t)bm * K_DIM;
    const __half* gB0 = g_B + (size_t)bn * K_DIM;

    auto load_stage = [&](int slot, int t) {
        const uint32_t sa  = sb + slot * STAGE_BYTES;
        const uint32_t sbs = sa + STAGE_A;
        const __half* gA = gA0 + t * BKH;
        const __half* gB = gB0 + t * BKH;
        #pragma unroll
        for (int i = 0; i < 8; i++) {
            int id = i * 128 + tid;
            int r = id >> 3, cc = id & 7;
            cp16(sa + r * 128 + ((cc ^ (r & 7)) << 4), gA + (size_t)r * K_DIM + cc * 8);
        }
        #pragma unroll
        for (int i = 0; i < 8; i++) {
            int id = i * 128 + tid;
            int r = id >> 3, cc = id & 7;
            cp16(sbs + r * 128 + ((cc ^ (r & 7)) << 4), gB + (size_t)r * K_DIM + cc * 8);
        }
        asm volatile("cp.async.commit_group;");
    };

    load_stage(0, 0);
    load_stage(1, 1);

    const int t4 = lane >> 3;             // ldmatrix tile index 0..3
    const int rs = lane & 7;              // row within 8x8 tile

    const int a_row_base = wm + ((t4 & 1) << 3) + rs;    // + mi*16
    const int a_ch_bit   = t4 >> 1;                      // chunk = 2kk + this
    const int b_row_base = wn + ((t4 >> 1) << 3) + rs;   // + nb*16
    const int b_ch_bit   = t4 & 1;

    uint32_t a[2][4][4], b[2][8][2];

    auto ld_frags = [&](int buf, uint32_t sa, uint32_t sbs, int kk) {
        #pragma unroll
        for (int mi = 0; mi < 4; mi++) {
            int row = a_row_base + mi * 16;
            int ch  = 2 * kk + a_ch_bit;
            ldsm4(a[buf][mi][0], a[buf][mi][1], a[buf][mi][2], a[buf][mi][3],
                  sa + row * 128 + ((ch ^ (row & 7)) << 4));
        }
        #pragma unroll
        for (int nb = 0; nb < 4; nb++) {
            int nrow = b_row_base + nb * 16;
            int ch   = 2 * kk + b_ch_bit;
            ldsm4(b[buf][2 * nb][0], b[buf][2 * nb][1],
                  b[buf][2 * nb + 1][0], b[buf][2 * nb + 1][1],
                  sbs + nrow * 128 + ((ch ^ (nrow & 7)) << 4));
        }
    };

    for (int t = 0; t < KT; t++) {
        if (t < KT - 1) asm volatile("cp.async.wait_group 1;");
        else            asm volatile("cp.async.wait_group 0;");
        __syncthreads();

        const uint32_t sa  = sb + (t % NSTAGES) * STAGE_BYTES;
        const uint32_t sbs = sa + STAGE_A;

        // restart the tensor pipe first; next stage's cp.async issues after
        // the kk=0 MMA block (hidden under chunk-1 MMA execution).
        ld_frags(0, sa, sbs, 0);

        #pragma unroll
        for (int kk = 0; kk < 4; kk++) {      // 4 x k16 chunks, reg double buffer
            const int cur = kk & 1;
            if (kk < 3) ld_frags(cur ^ 1, sa, sbs, kk + 1);
            #pragma unroll
            for (int mi = 0; mi < 4; mi++)
                #pragma unroll
                for (int ni = 0; ni < 8; ni++)
                    asm volatile(
                        "mma.sync.aligned.m16n8k16.row.col.f32.f16.f16.f32 "
                        "{%0,%1,%2,%3}, {%4,%5,%6,%7}, {%8,%9}, {%0,%1,%2,%3};"
                        : "+f"(c[mi][ni][0]), "+f"(c[mi][ni][1]),
                          "+f"(c[mi][ni][2]), "+f"(c[mi][ni][3])
                        : "r"(a[cur][mi][0]), "r"(a[cur][mi][1]),
                          "r"(a[cur][mi][2]), "r"(a[cur][mi][3]),
                          "r"(b[cur][ni][0]), "r"(b[cur][ni][1]));
            if (kk == 0 && t + 2 < KT) load_stage((t + 2) % NSTAGES, t + 2);
        }
        // next iteration's top barrier orders compute(t) before load(t+3)
        // overwrites slot t%3.
    }

    // epilogue: bias add + fp32 store
    #pragma unroll
    for (int mi = 0; mi < 4; mi++) {
        const int row = bm + wm + mi * 16 + (lane >> 2);
        #pragma unroll
        for (int ni = 0; ni < 8; ni++) {
            const int col = bn + wn + ni * 8 + 2 * (lane & 3);
            const float2 bv = *reinterpret_cast<const float2*>(bias + col);
            float2 r0 = make_float2(c[mi][ni][0] + bv.x, c[mi][ni][1] + bv.y);
            float2 r1 = make_float2(c[mi][ni][2] + bv.x, c[mi][ni][3] + bv.y);
            *reinterpret_cast<float2*>(out + (size_t)row * N_DIM + col) = r0;
            *reinterpret_cast<float2*>(out + (size_t)(row + 8) * N_DIM + col) = r1;
        }
    }
}

// ---------------------------------------------------------------------------
extern "C" void kernel_launch(void* const* d_in, const int* in_sizes, int n_in,
                              void* d_out, int out_size) {
    const float* x         = (const float*)d_in[0];
    const float* centroids = (const float*)d_in[1];
    const void*  labels    = d_in[2];
    const float* scale     = (const float*)d_in[3];
    const float* bias      = (const float*)d_in[4];
    float* out = (float*)d_out;

    const int M = in_sizes[0] / K_DIM;   // 8192

    setup_kernel<<<K_DIM / 256, 256>>>((const int*)labels, scale);
    dequant_kernel<<<dim3(K_DIM / 64, N_DIM / 128), 256>>>(centroids, labels, scale);
    const int n8 = (M * K_DIM) / 8;
    round_x_kernel<<<(n8 + 255) / 256, 256>>>(x, n8);

    const size_t smem = (size_t)NSTAGES * STAGE_BYTES;   // 98304 B
    cudaFuncSetAttribute(gemm_kernel, cudaFuncAttributeMaxDynamicSharedMemorySize, (int)smem);
    gemm_kernel<<<dim3(N_DIM / BN, M / BM), NTHREADS, smem>>>(bias, out);
}

// round 13
// speedup vs baseline: 1.0709x; 1.0709x over previous
#include <cuda_runtime.h>
#include <cuda_fp16.h>
#include <cstdint>

#define K_DIM 4096
#define N_DIM 4096
#define NG    512
#define M_MAX 8192

// ---- GEMM tiling (fp16 operands) ----
#define BM 128
#define BN 128
#define BKH 64                  // halves per k-stage = 128 B per row (SW128 domain)
#define NSTAGES 3
#define NTHREADS 128            // 4 warps, each 64x64
#define STAGE_A 16384           // 128 rows x 128 B
#define STAGE_B 16384
#define STAGE_BYTES (STAGE_A + STAGE_B)

#define HCLAMP 65472.0f

// Scratch (static __device__: allowed)
__device__ __half g_X[(size_t)M_MAX * K_DIM];   // x * alpha_k, fp16      [M,K]
__device__ __half g_B[(size_t)N_DIM * K_DIM];   // W / alpha_k, fp16, K-major [N,K]
__device__ float  g_alpha[K_DIM];               // per-k power-of-2 rebalance
__device__ int    g_lab64;

// ---------------- helpers ----------------
__device__ __forceinline__ uint32_t smem_u32(const void* p) {
    uint32_t a;
    asm("{ .reg .u64 t; cvta.to.shared.u64 t, %1; cvt.u32.u64 %0, t; }" : "=r"(a) : "l"(p));
    return a;
}
__device__ __forceinline__ void cp16(uint32_t saddr, const void* g) {
    asm volatile("cp.async.cg.shared.global [%0], [%1], 16;" :: "r"(saddr), "l"(g));
}
__device__ __forceinline__ void ldsm4(uint32_t& r0, uint32_t& r1, uint32_t& r2, uint32_t& r3,
                                      uint32_t addr) {
    asm volatile("ldmatrix.sync.aligned.m8n8.x4.shared.b16 {%0,%1,%2,%3}, [%4];"
                 : "=r"(r0), "=r"(r1), "=r"(r2), "=r"(r3) : "r"(addr));
}
__device__ __forceinline__ float hclamp(float v) {
    return fminf(fmaxf(v, -HCLAMP), HCLAMP);
}
__device__ __forceinline__ uint32_t h2_bits(__half2 h) {
    uint32_t u;
    memcpy(&u, &h, 4);
    return u;
}

// ---------------------------------------------------------------------------
// setup: per-k alpha (all threads) + warp-ballot label dtype detection.
// alpha_k = 2^e, e = clamp(ceil(-log2(max(scale,1e-8))/2), 0, 12)
// Detection: int64 LE labels < 65536 => every odd int32 word == 0. The 64
// probe words are loaded by one warp in parallel (one L2 trip, not 64).
// ---------------------------------------------------------------------------
__global__ void setup_kernel(const int* __restrict__ labels32,
                             const float* __restrict__ scale) {
    int k = blockIdx.x * blockDim.x + threadIdx.x;
    if (k < K_DIM) {
        float s = fmaxf(scale[k], 1e-8f);
        int e = (int)ceilf(-0.5f * log2f(s));
        e = max(0, min(12, e));
        g_alpha[k] = (float)(1u << e);
    }
    if (blockIdx.x == 0 && threadIdx.x < 32) {
        int t = threadIdx.x;
        int w0 = labels32[2 * t + 1];
        int w1 = labels32[2 * (t + 32) + 1];
        unsigned m = __ballot_sync(0xFFFFFFFFu, (w0 | w1) != 0);
        if (t == 0) g_lab64 = (m == 0) ? 1 : 0;
    }
}

// ---------------------------------------------------------------------------
// dequant + transpose: g_B[n][k] = fp16( centroids[labels[k,n/8]][n%8] /
//                                        (max(scale[k],1e-8) * alpha_k) )
// ---------------------------------------------------------------------------
__global__ void __launch_bounds__(256) dequant_kernel(const float* __restrict__ centroids,
                                                      const void* __restrict__ labels_raw,
                                                      const float* __restrict__ scale) {
    __shared__ float tile[128][65];
    const int tid = threadIdx.x;
    const int k0 = blockIdx.x * 64;
    const int n0 = blockIdx.y * 128;
    const int g0 = n0 >> 3;
    const bool l64 = (g_lab64 != 0);

    #pragma unroll
    for (int it = 0; it < 4; it++) {
        int id = it * 256 + tid;          // 1024 items: 64 k x 16 groups
        int kl = id >> 4, g = id & 15;
        int k = k0 + kl;
        long long lab = l64 ? ((const long long*)labels_raw)[(size_t)k * NG + g0 + g]
                            : (long long)((const int*)labels_raw)[(size_t)k * NG + g0 + g];
        float rs = 1.0f / (fmaxf(__ldg(scale + k), 1e-8f) * g_alpha[k]);
        const float4* c = reinterpret_cast<const float4*>(centroids + (size_t)lab * 8);
        float4 v0 = __ldg(c), v1 = __ldg(c + 1);
        int nb = g * 8;
        tile[nb + 0][kl] = v0.x * rs; tile[nb + 1][kl] = v0.y * rs;
        tile[nb + 2][kl] = v0.z * rs; tile[nb + 3][kl] = v0.w * rs;
        tile[nb + 4][kl] = v1.x * rs; tile[nb + 5][kl] = v1.y * rs;
        tile[nb + 6][kl] = v1.z * rs; tile[nb + 7][kl] = v1.w * rs;
    }
    __syncthreads();
    #pragma unroll
    for (int it = 0; it < 8; it++) {
        int id = it * 256 + tid;          // 2048 items: 128 n x 16 k-quads
        int nl = id >> 4, k4 = (id & 15) * 4;
        __half2 h0 = __floats2half2_rn(hclamp(tile[nl][k4]),     hclamp(tile[nl][k4 + 1]));
        __half2 h1 = __floats2half2_rn(hclamp(tile[nl][k4 + 2]), hclamp(tile[nl][k4 + 3]));
        uint2 v = make_uint2(h2_bits(h0), h2_bits(h1));
        *reinterpret_cast<uint2*>(g_B + (size_t)(n0 + nl) * K_DIM + k0 + k4) = v;
    }
}

// ---------------------------------------------------------------------------
// x' = fp16(x * alpha_k): 8 halves per thread
// ---------------------------------------------------------------------------
__global__ void round_x_kernel(const float* __restrict__ x, int n8) {
    int idx = blockIdx.x * blockDim.x + threadIdx.x;
    if (idx >= n8) return;
    const int kb = (idx * 8) & (K_DIM - 1);
    float4 a = __ldg(reinterpret_cast<const float4*>(x) + idx * 2);
    float4 b = __ldg(reinterpret_cast<const float4*>(x) + idx * 2 + 1);
    float4 al0 = *reinterpret_cast<const float4*>(g_alpha + kb);
    float4 al1 = *reinterpret_cast<const float4*>(g_alpha + kb + 4);
    __half2 h0 = __floats2half2_rn(hclamp(a.x * al0.x), hclamp(a.y * al0.y));
    __half2 h1 = __floats2half2_rn(hclamp(a.z * al0.z), hclamp(a.w * al0.w));
    __half2 h2 = __floats2half2_rn(hclamp(b.x * al1.x), hclamp(b.y * al1.y));
    __half2 h3 = __floats2half2_rn(hclamp(b.z * al1.z), hclamp(b.w * al1.w));
    uint4 v = make_uint4(h2_bits(h0), h2_bits(h1), h2_bits(h2), h2_bits(h3));
    reinterpret_cast<uint4*>(g_X)[idx] = v;
}

// ---------------------------------------------------------------------------
// GEMM: out = g_X @ g_B^T + bias.  128x128 CTA tile, 4 warps of 64x64,
// BK=64 halves, 3-stage cp.async, SW128 swizzled smem, ldmatrix with
// register-level double buffering, m16n8k16 fp16 mma.sync, fp32 accumulate.
// (Exact R8 structure: ld_frags(0) then full cp.async burst, then MMA loop.)
// ---------------------------------------------------------------------------
__global__ void __launch_bounds__(NTHREADS, 2)
gemm_kernel(const float* __restrict__ bias, float* __restrict__ out) {
    extern __shared__ char smem_raw[];
    const uint32_t sb = smem_u32(smem_raw);

    const int tid  = threadIdx.x;
    const int wid  = tid >> 5;
    const int lane = tid & 31;
    const int bm = blockIdx.y * BM;
    const int bn = blockIdx.x * BN;
    const int wm = (wid & 1) * 64;        // warp tile 64 (m) x 64 (n)
    const int wn = (wid >> 1) * 64;

    float c[4][8][4];
    #pragma unroll
    for (int mi = 0; mi < 4; mi++)
        #pragma unroll
        for (int ni = 0; ni < 8; ni++) {
            c[mi][ni][0] = 0.f; c[mi][ni][1] = 0.f;
            c[mi][ni][2] = 0.f; c[mi][ni][3] = 0.f;
        }

    const int KT = K_DIM / BKH;           // 64

    const __half* gA0 = g_X + (size_t)bm * K_DIM;
    const __half* gB0 = g_B + (size_t)bn * K_DIM;

    auto load_stage = [&](int slot, int t) {
        const uint32_t sa  = sb + slot * STAGE_BYTES;
        const uint32_t sbs = sa + STAGE_A;
        const __half* gA = gA0 + t * BKH;
        const __half* gB = gB0 + t * BKH;
        #pragma unroll
        for (int i = 0; i < 8; i++) {
            int id = i * 128 + tid;
            int r = id >> 3, cc = id & 7;
            cp16(sa + r * 128 + ((cc ^ (r & 7)) << 4), gA + (size_t)r * K_DIM + cc * 8);
        }
        #pragma unroll
        for (int i = 0; i < 8; i++) {
            int id = i * 128 + tid;
            int r = id >> 3, cc = id & 7;
            cp16(sbs + r * 128 + ((cc ^ (r & 7)) << 4), gB + (size_t)r * K_DIM + cc * 8);
        }
        asm volatile("cp.async.commit_group;");
    };

    load_stage(0, 0);
    load_stage(1, 1);

    const int t4 = lane >> 3;             // ldmatrix tile index 0..3
    const int rs = lane & 7;              // row within 8x8 tile

    const int a_row_base = wm + ((t4 & 1) << 3) + rs;    // + mi*16
    const int a_ch_bit   = t4 >> 1;                      // chunk = 2kk + this
    const int b_row_base = wn + ((t4 >> 1) << 3) + rs;   // + nb*16
    const int b_ch_bit   = t4 & 1;

    uint32_t a[2][4][4], b[2][8][2];

    auto ld_frags = [&](int buf, uint32_t sa, uint32_t sbs, int kk) {
        #pragma unroll
        for (int mi = 0; mi < 4; mi++) {
            int row = a_row_base + mi * 16;
            int ch  = 2 * kk + a_ch_bit;
            ldsm4(a[buf][mi][0], a[buf][mi][1], a[buf][mi][2], a[buf][mi][3],
                  sa + row * 128 + ((ch ^ (row & 7)) << 4));
        }
        #pragma unroll
        for (int nb = 0; nb < 4; nb++) {
            int nrow = b_row_base + nb * 16;
            int ch   = 2 * kk + b_ch_bit;
            ldsm4(b[buf][2 * nb][0], b[buf][2 * nb][1],
                  b[buf][2 * nb + 1][0], b[buf][2 * nb + 1][1],
                  sbs + nrow * 128 + ((ch ^ (nrow & 7)) << 4));
        }
    };

    for (int t = 0; t < KT; t++) {
        if (t < KT - 1) asm volatile("cp.async.wait_group 1;");
        else            asm volatile("cp.async.wait_group 0;");
        __syncthreads();

        const uint32_t sa  = sb + (t % NSTAGES) * STAGE_BYTES;
        const uint32_t sbs = sa + STAGE_A;

        // restart the tensor pipe first, then issue next stage's cp.async
        ld_frags(0, sa, sbs, 0);
        if (t + 2 < KT) load_stage((t + 2) % NSTAGES, t + 2);

        #pragma unroll
        for (int kk = 0; kk < 4; kk++) {      // 4 x k16 chunks, reg double buffer
            const int cur = kk & 1;
            if (kk < 3) ld_frags(cur ^ 1, sa, sbs, kk + 1);
            #pragma unroll
            for (int mi = 0; mi < 4; mi++)
                #pragma unroll
                for (int ni = 0; ni < 8; ni++)
                    asm volatile(
                        "mma.sync.aligned.m16n8k16.row.col.f32.f16.f16.f32 "
                        "{%0,%1,%2,%3}, {%4,%5,%6,%7}, {%8,%9}, {%0,%1,%2,%3};"
                        : "+f"(c[mi][ni][0]), "+f"(c[mi][ni][1]),
                          "+f"(c[mi][ni][2]), "+f"(c[mi][ni][3])
                        : "r"(a[cur][mi][0]), "r"(a[cur][mi][1]),
                          "r"(a[cur][mi][2]), "r"(a[cur][mi][3]),
                          "r"(b[cur][ni][0]), "r"(b[cur][ni][1]));
        }
        // next iteration's top barrier orders compute(t) before load(t+3)
        // overwrites slot t%3.
    }

    // epilogue: bias add + fp32 store
    #pragma unroll
    for (int mi = 0; mi < 4; mi++) {
        const int row = bm + wm + mi * 16 + (lane >> 2);
        #pragma unroll
        for (int ni = 0; ni < 8; ni++) {
            const int col = bn + wn + ni * 8 + 2 * (lane & 3);
            const float2 bv = *reinterpret_cast<const float2*>(bias + col);
            float2 r0 = make_float2(c[mi][ni][0] + bv.x, c[mi][ni][1] + bv.y);
            float2 r1 = make_float2(c[mi][ni][2] + bv.x, c[mi][ni][3] + bv.y);
            *reinterpret_cast<float2*>(out + (size_t)row * N_DIM + col) = r0;
            *reinterpret_cast<float2*>(out + (size_t)(row + 8) * N_DIM + col) = r1;
        }
    }
}

// ---------------------------------------------------------------------------
extern "C" void kernel_launch(void* const* d_in, const int* in_sizes, int n_in,
                              void* d_out, int out_size) {
    const float* x         = (const float*)d_in[0];
    const float* centroids = (const float*)d_in[1];
    const void*  labels    = d_in[2];
    const float* scale     = (const float*)d_in[3];
    const float* bias      = (const float*)d_in[4];
    float* out = (float*)d_out;

    const int M = in_sizes[0] / K_DIM;   // 8192

    setup_kernel<<<K_DIM / 256, 256>>>((const int*)labels, scale);
    dequant_kernel<<<dim3(K_DIM / 64, N_DIM / 128), 256>>>(centroids, labels, scale);
    const int n8 = (M * K_DIM) / 8;
    round_x_kernel<<<(n8 + 255) / 256, 256>>>(x, n8);

    const size_t smem = (size_t)NSTAGES * STAGE_BYTES;   // 98304 B
    cudaFuncSetAttribute(gemm_kernel, cudaFuncAttributeMaxDynamicSharedMemorySize, (int)smem);
    gemm_kernel<<<dim3(N_DIM / BN, M / BM), NTHREADS, smem>>>(bias, out);
}